// round 9
// baseline (speedup 1.0000x reference)
#include <cuda_runtime.h>
#include <cuda_bf16.h>

#define BATCH 16
#define N 256
#define DIM 128

// Scratch (device globals: allocation-free per harness rules)
__device__ float          g_dist[BATCH * N * N];   // 4 MB fp32 distances
__device__ unsigned short g_cost[BATCH * N * N];   // 2 MB u16 quantized costs
__device__ double         g_bsum[BATCH];           // per-batch matched sums

#define QSCALE 512.0f
#define QMAX   16383          // 14-bit D field ceiling

// ---------------------------------------------------------------------------
// Kernel A: pairwise L2 distances + quantization. 16x16 tile per block.
// ---------------------------------------------------------------------------
__global__ __launch_bounds__(256) void dist_kernel(const float* __restrict__ pred,
                                                   const float* __restrict__ tgt) {
    __shared__ float sp[16 * 132];
    __shared__ float st[16 * 132];
    const int b  = blockIdx.z;
    const int rt = blockIdx.y;
    const int ct = blockIdx.x;
    const int tid = threadIdx.x;

    const float4* p4 = (const float4*)(pred + (size_t)(b * N + rt * 16) * DIM);
    const float4* t4 = (const float4*)(tgt  + (size_t)(b * N + ct * 16) * DIM);
    for (int idx = tid; idx < 512; idx += 256) {
        int r = idx >> 5, c = idx & 31;
        *(float4*)&sp[r * 132 + c * 4] = p4[idx];
        *(float4*)&st[r * 132 + c * 4] = t4[idx];
    }
    __syncthreads();

    const int ti = tid >> 4;
    const int tj = tid & 15;
    float acc = 0.f;
#pragma unroll
    for (int d4 = 0; d4 < 32; ++d4) {
        float4 a = *(const float4*)&sp[ti * 132 + d4 * 4];
        float4 c = *(const float4*)&st[tj * 132 + d4 * 4];
        float dx = a.x - c.x, dy = a.y - c.y, dz = a.z - c.z, dw = a.w - c.w;
        acc += dx * dx + dy * dy + dz * dz + dw * dw;
    }
    float dd = sqrtf(acc);
    size_t o = ((size_t)b << 16) + (size_t)(rt * 16 + ti) * N + (ct * 16 + tj);
    g_dist[o] = dd;
    int q = __float2int_rn(dd * QSCALE);
    g_cost[o] = (unsigned short)(q > QMAX ? QMAX : q);
}

// ---------------------------------------------------------------------------
// Kernel B: per-batch Jonker-Volgenant LSA on u16 costs in shared.
//   Warp-0 Dijkstra, (D<<17|p<<8|j) packed redux-min. Critical path carries
//   only: LDS row -> cand -> treeCand -> min(treeOld) -> REDUX. Dp / wayreg /
//   freeze / treeOld maintenance runs in the LDS shadow; the break iteration
//   ALSO applies the Dp/wayreg relaxation (bugfix R8: terminal relaxation
//   was dropped, corrupting the augmenting path). Frozen columns carry bit31
//   in pkj (future cands live in [2^31,2^32): never win, never overwrite the
//   frozen Dp), plus fzm for treeOld exclusion.
// ---------------------------------------------------------------------------
// dynamic smem layout (bytes)
#define OFF_COST 0                       // u16[65536] = 131072
#define OFF_U    131072                  // int[257]   = 1028  -> 132100
#define OFF_P    132100                  // u16[257]   = 514   -> 132614
#define OFF_WAY  132624                  // u16[256]   = 512   -> 133136 (16-aligned)
#define OFF_RMIN 133136                  // u16[256]   = 512   -> 133648 (16-aligned)
#define OFF_ROWT 133648                  // u32[8]     = 32    -> 133680
#define OFF_SRED 133680                  // double[8]  = 64    -> 133744
#define SMEM_B   133744

#define JROOT 0x1FF                      // way-chain root marker

extern __shared__ char s_raw[];

__global__ __launch_bounds__(256) void hungarian_kernel() {
    const int b   = blockIdx.x;
    const int tid = threadIdx.x;

    unsigned short* cost  = (unsigned short*)(s_raw + OFF_COST);
    int*            u_    = (int*)(s_raw + OFF_U);        // 1-based rows
    unsigned short* p_    = (unsigned short*)(s_raw + OFF_P);   // p_[j+1], 0 = free
    unsigned short* way0_ = (unsigned short*)(s_raw + OFF_WAY); // 0-based cols
    unsigned short* srmin = (unsigned short*)(s_raw + OFF_RMIN);
    unsigned*       srowt = (unsigned*)(s_raw + OFF_ROWT);
    double*         sred  = (double*)(s_raw + OFF_SRED);

    // ---- Phase 1: copy quantized costs into shared, init state ----
    const uint4* csrc = (const uint4*)(g_cost + ((size_t)b << 16));
    uint4* cdst = (uint4*)cost;
    for (int idx = tid; idx < (N * N) / 8; idx += 256) cdst[idx] = csrc[idx];
    for (int i = tid; i < N + 1; i += 256) { u_[i] = 0; p_[i] = 0; }
    __syncthreads();

    // ---- Phase 2: warp 0 runs the LSA ----
    if (tid < 32) {
        const unsigned FULL = 0xffffffffu;
        const int lane = tid;

        // Column reduction: v[j] = min_i cost[i][j], rmin[j] = first argmin row.
        unsigned vmin[8]; int rmin[8];
#pragma unroll
        for (int k = 0; k < 8; ++k) { vmin[k] = 0xFFFFFFFFu; rmin[k] = 0; }
        for (int r = 0; r < N; ++r) {
            uint4 cc = ((const uint4*)(cost + (r << 8)))[lane];
            unsigned wv[4] = {cc.x, cc.y, cc.z, cc.w};
#pragma unroll
            for (int k = 0; k < 8; ++k) {
                unsigned c = (wv[k >> 1] >> ((k & 1) * 16)) & 0xFFFFu;
                if (c < vmin[k]) { vmin[k] = c; rmin[k] = r; }
            }
        }
        {
            unsigned a0 = (unsigned)rmin[0] | ((unsigned)rmin[1] << 16);
            unsigned a1 = (unsigned)rmin[2] | ((unsigned)rmin[3] << 16);
            unsigned a2 = (unsigned)rmin[4] | ((unsigned)rmin[5] << 16);
            unsigned a3 = (unsigned)rmin[6] | ((unsigned)rmin[7] << 16);
            ((uint4*)srmin)[lane] = make_uint4(a0, a1, a2, a3);
        }
        if (lane < 8) srowt[lane] = 0u;
        __syncwarp();
        // Greedy pre-assignment: column j -> rmin[j] if that row is still free.
        if (lane == 0) {
            for (int j = 0; j < N; ++j) {
                int r = srmin[j];
                unsigned wd = srowt[r >> 5];
                if (!((wd >> (r & 31)) & 1u)) {
                    srowt[r >> 5] = wd | (1u << (r & 31));
                    p_[j + 1] = (unsigned short)(r + 1);
                }
            }
        }
        __syncwarp();

        int vreg[8];
#pragma unroll
        for (int k = 0; k < 8; ++k) vreg[k] = (int)vmin[k];
        unsigned rt[8];
#pragma unroll
        for (int w = 0; w < 8; ++w) rt[w] = srowt[w];

        // base pointer for this lane's 16-byte row slice (offset by t_i*2-512)
        const char* cbase = (const char*)cost - 512 + lane * 16;

        // ---- Dijkstra for each unassigned row ----
        for (int w = 0; w < 8; ++w) {
            unsigned freeb = ~rt[w];
            while (freeb) {
                const int bz = __ffs(freeb) - 1;
                freeb &= freeb - 1;
                const int i = w * 32 + bz + 1;     // 1-based start row; u_[i]==0

                unsigned pkj[8], Dp[8], fzm[8];
                int wayreg[8];
#pragma unroll
                for (int k = 0; k < 8; ++k) {
                    int j = (lane << 3) + k;
                    pkj[k] = ((unsigned)p_[j + 1] << 8) | (unsigned)j;
                    Dp[k] = 0xFFFFFFFFu;
                    fzm[k] = 0u;
                    wayreg[k] = JROOT;
                }

                unsigned treeOld = 0xFFFFFFFFu;
                unsigned t_i = (unsigned)i << 8;   // = i0 * 256 (decoded field)
                int S = 0, u0 = 0, j0 = JROOT, jfinal;

                while (true) {
                    // -- critical path: row load -> cand -> treeCand -> redux --
                    const uint4 cc = *(const uint4*)(cbase + t_i * 2);
                    const int baseS = S - u0;
                    unsigned wv[4] = {cc.x, cc.y, cc.z, cc.w};
                    unsigned cand[8];
#pragma unroll
                    for (int k = 0; k < 8; ++k) {
                        int c = (int)((wv[k >> 1] >> ((k & 1) * 16)) & 0xFFFFu);
                        int d = baseS + c - vreg[k];       // >= S >= 0
                        d = d > QMAX ? QMAX : d;           // winners never clamped
                        cand[k] = (unsigned)d * 131072u + pkj[k];  // IMAD pack
                    }
                    unsigned c01 = cand[0] < cand[1] ? cand[0] : cand[1];
                    unsigned c23 = cand[2] < cand[3] ? cand[2] : cand[3];
                    unsigned c45 = cand[4] < cand[5] ? cand[4] : cand[5];
                    unsigned c67 = cand[6] < cand[7] ? cand[6] : cand[7];
                    unsigned ca = c01 < c23 ? c01 : c23;
                    unsigned cb = c45 < c67 ? c45 : c67;
                    unsigned tc = ca < cb ? ca : cb;
                    unsigned m = tc < treeOld ? tc : treeOld;
                    const unsigned g = __reduce_min_sync(FULL, m);

                    // -- decode --
                    t_i = g & 0x1FF00u;                    // p * 256
                    S   = (int)(g >> 17);
                    const int j1 = (int)(g & 0xFFu);
                    if (t_i == 0) {
                        // BUGFIX: apply the terminal relaxation so the winning
                        // free column's predecessor (wayreg) is current.
                        jfinal = j1;
#pragma unroll
                        for (int k = 0; k < 8; ++k)
                            if (cand[k] < Dp[k]) { Dp[k] = cand[k]; wayreg[k] = j0; }
                        break;
                    }
                    u0  = *(const int*)((const char*)u_ + (t_i >> 6));

                    // -- shadow work (overlaps decode + next LDS) --
#pragma unroll
                    for (int k = 0; k < 8; ++k)
                        if (((lane << 3) + k) == j1) {
                            pkj[k] |= 0x80000000u;         // frozen: cands never win
                            fzm[k]  = 0x80000000u;         // exclude from treeOld
                        }
#pragma unroll
                    for (int k = 0; k < 8; ++k)
                        if (cand[k] < Dp[k]) { Dp[k] = cand[k]; wayreg[k] = j0; }
                    {
                        unsigned x0 = Dp[0] | fzm[0], x1 = Dp[1] | fzm[1];
                        unsigned x2 = Dp[2] | fzm[2], x3 = Dp[3] | fzm[3];
                        unsigned x4 = Dp[4] | fzm[4], x5 = Dp[5] | fzm[5];
                        unsigned x6 = Dp[6] | fzm[6], x7 = Dp[7] | fzm[7];
                        unsigned m01 = x0 < x1 ? x0 : x1;
                        unsigned m23 = x2 < x3 ? x2 : x3;
                        unsigned m45 = x4 < x5 ? x4 : x5;
                        unsigned m67 = x6 < x7 ? x6 : x7;
                        unsigned maa = m01 < m23 ? m01 : m23;
                        unsigned mbb = m45 < m67 ? m45 : m67;
                        treeOld = maa < mbb ? maa : mbb;
                    }
                    j0 = j1;
                }

                const int mu = S;
                // publish way pointers (wayreg freeze-clean: frozen cands >= 2^31)
                {
                    unsigned a0 = ((unsigned)wayreg[0] & 0xFFFFu) | ((unsigned)wayreg[1] << 16);
                    unsigned a1 = ((unsigned)wayreg[2] & 0xFFFFu) | ((unsigned)wayreg[3] << 16);
                    unsigned a2 = ((unsigned)wayreg[4] & 0xFFFFu) | ((unsigned)wayreg[5] << 16);
                    unsigned a3 = ((unsigned)wayreg[6] & 0xFFFFu) | ((unsigned)wayreg[7] << 16);
                    ((uint4*)way0_)[lane] = make_uint4(a0, a1, a2, a3);
                }
                __syncwarp();
                if (lane == 0) {
                    int cur = jfinal;                      // augment along path
                    while (true) {
                        int pr = way0_[cur];
                        if (pr == JROOT) { p_[cur + 1] = (unsigned short)i; break; }
                        p_[cur + 1] = p_[pr + 1];
                        cur = pr;
                    }
                    u_[i] += mu;
                }
                // deferred dual updates, decoded from frozen Dp words
#pragma unroll
                for (int k = 0; k < 8; ++k)
                    if (fzm[k]) {
                        unsigned dk = Dp[k];
                        int adj = mu - (int)(dk >> 17);
                        vreg[k] -= adj;
                        u_[(dk >> 8) & 0x1FFu] += adj;
                    }
                __syncwarp();
            }
        }
    }
    __syncthreads();

    // ---- Phase 3: gather matched fp32 distances, deterministic block sum ----
    {
        const int j   = tid + 1;
        const int row = p_[j];
        float val = g_dist[((size_t)b << 16) + (size_t)(row - 1) * N + (j - 1)];
        double d = (double)val;
#pragma unroll
        for (int off = 16; off > 0; off >>= 1)
            d += __shfl_down_sync(0xffffffffu, d, off);
        if ((tid & 31) == 0) sred[tid >> 5] = d;
        __syncthreads();
        if (tid == 0) {
            double t = 0.0;
#pragma unroll
            for (int w = 0; w < 8; ++w) t += sred[w];   // fixed order
            g_bsum[b] = t;
        }
    }
}

// ---------------------------------------------------------------------------
// Kernel C: deterministic final reduce + mean
// ---------------------------------------------------------------------------
__global__ void finalize_kernel(float* __restrict__ out) {
    double t = 0.0;
#pragma unroll
    for (int b = 0; b < BATCH; ++b) t += g_bsum[b];
    out[0] = (float)(t / (double)(BATCH * N));
}

// ---------------------------------------------------------------------------
extern "C" void kernel_launch(void* const* d_in, const int* in_sizes, int n_in,
                              void* d_out, int out_size) {
    const float* pred = (const float*)d_in[0];
    const float* tgt  = (const float*)d_in[1];
    float* out = (float*)d_out;

    cudaFuncSetAttribute(hungarian_kernel,
                         cudaFuncAttributeMaxDynamicSharedMemorySize, SMEM_B);

    dist_kernel<<<dim3(16, 16, 16), 256>>>(pred, tgt);
    hungarian_kernel<<<BATCH, 256, SMEM_B>>>();
    finalize_kernel<<<1, 1>>>(out);
}

// round 10
// speedup vs baseline: 1.3438x; 1.3438x over previous
#include <cuda_runtime.h>
#include <cuda_bf16.h>

#define BATCH 16
#define N 256
#define DIM 128

// Scratch (device globals: allocation-free per harness rules)
__device__ float          g_dist[BATCH * N * N];   // 4 MB fp32 distances
__device__ unsigned short g_cost[BATCH * N * N];   // 2 MB u16 quantized costs
__device__ double         g_bsum[BATCH];           // per-batch matched sums

#define QSCALE 256.0f
#define QMAX   8191           // 13-bit cost => d = S + rc < 2^14, bit31 tag wrap-free

// ---------------------------------------------------------------------------
// Kernel A: pairwise L2 distances + quantization. 16x16 tile per block.
// ---------------------------------------------------------------------------
__global__ __launch_bounds__(256) void dist_kernel(const float* __restrict__ pred,
                                                   const float* __restrict__ tgt) {
    __shared__ float sp[16 * 132];
    __shared__ float st[16 * 132];
    const int b  = blockIdx.z;
    const int rt = blockIdx.y;
    const int ct = blockIdx.x;
    const int tid = threadIdx.x;

    const float4* p4 = (const float4*)(pred + (size_t)(b * N + rt * 16) * DIM);
    const float4* t4 = (const float4*)(tgt  + (size_t)(b * N + ct * 16) * DIM);
    for (int idx = tid; idx < 512; idx += 256) {
        int r = idx >> 5, c = idx & 31;
        *(float4*)&sp[r * 132 + c * 4] = p4[idx];
        *(float4*)&st[r * 132 + c * 4] = t4[idx];
    }
    __syncthreads();

    const int ti = tid >> 4;
    const int tj = tid & 15;
    float acc = 0.f;
#pragma unroll
    for (int d4 = 0; d4 < 32; ++d4) {
        float4 a = *(const float4*)&sp[ti * 132 + d4 * 4];
        float4 c = *(const float4*)&st[tj * 132 + d4 * 4];
        float dx = a.x - c.x, dy = a.y - c.y, dz = a.z - c.z, dw = a.w - c.w;
        acc += dx * dx + dy * dy + dz * dz + dw * dw;
    }
    float dd = sqrtf(acc);
    size_t o = ((size_t)b << 16) + (size_t)(rt * 16 + ti) * N + (ct * 16 + tj);
    g_dist[o] = dd;
    int q = __float2int_rn(dd * QSCALE);
    g_cost[o] = (unsigned short)(q > QMAX ? QMAX : q);
}

// ---------------------------------------------------------------------------
// Kernel B: per-batch Jonker-Volgenant LSA on u16 costs in shared.
//   Warp-0 Dijkstra, (d<<17 | p<<8 | j) packed redux-min, inline relax.
//   Issue-minimized step: pre-shifted extraction (w<<17 / (w<<1)&mask),
//   cand = pre + bsh + vpk (1 IADD3/col), Dp via VIMNMX (no predicates),
//   way via ISETP/SEL. Freeze: vpk += 2^31 (cands wrap-free >= 2^31,
//   never win, never beat frozen Dp since d >= S_now >= S_fz) and
//   Dp |= 2^31 (tree exclusion). Duals decoded from frozen Dp at end.
// ---------------------------------------------------------------------------
// dynamic smem layout (bytes)
#define OFF_COST 0                       // u16[65536] = 131072
#define OFF_U    131072                  // int[257]   = 1028  -> 132100
#define OFF_P    132100                  // u16[257]   = 514   -> 132614
#define OFF_WAY  132624                  // u16[256]   = 512   -> 133136 (16-aligned)
#define OFF_RMIN 133136                  // u16[256]   = 512   -> 133648 (16-aligned)
#define OFF_ROWT 133648                  // u32[8]     = 32    -> 133680
#define OFF_SRED 133680                  // double[8]  = 64    -> 133744
#define SMEM_B   133744

#define JROOT 0x1FF                      // way-chain root marker

extern __shared__ char s_raw[];

__global__ __launch_bounds__(256) void hungarian_kernel() {
    const int b   = blockIdx.x;
    const int tid = threadIdx.x;

    unsigned short* cost  = (unsigned short*)(s_raw + OFF_COST);
    int*            u_    = (int*)(s_raw + OFF_U);        // 1-based rows
    unsigned short* p_    = (unsigned short*)(s_raw + OFF_P);   // p_[j+1], 0 = free
    unsigned short* way0_ = (unsigned short*)(s_raw + OFF_WAY); // 0-based cols
    unsigned short* srmin = (unsigned short*)(s_raw + OFF_RMIN);
    unsigned*       srowt = (unsigned*)(s_raw + OFF_ROWT);
    double*         sred  = (double*)(s_raw + OFF_SRED);

    // ---- Phase 1: copy quantized costs into shared, init state ----
    const uint4* csrc = (const uint4*)(g_cost + ((size_t)b << 16));
    uint4* cdst = (uint4*)cost;
    for (int idx = tid; idx < (N * N) / 8; idx += 256) cdst[idx] = csrc[idx];
    for (int i = tid; i < N + 1; i += 256) { u_[i] = 0; p_[i] = 0; }
    __syncthreads();

    // ---- Phase 2: warp 0 runs the LSA ----
    if (tid < 32) {
        const unsigned FULL = 0xffffffffu;
        const int lane = tid;

        // Column reduction: v[j] = min_i cost[i][j], rmin[j] = first argmin row.
        unsigned vmin[8]; int rmin[8];
#pragma unroll
        for (int k = 0; k < 8; ++k) { vmin[k] = 0xFFFFFFFFu; rmin[k] = 0; }
        for (int r = 0; r < N; ++r) {
            uint4 cc = ((const uint4*)(cost + (r << 8)))[lane];
            unsigned wv[4] = {cc.x, cc.y, cc.z, cc.w};
#pragma unroll
            for (int k = 0; k < 8; ++k) {
                unsigned c = (wv[k >> 1] >> ((k & 1) * 16)) & 0xFFFFu;
                if (c < vmin[k]) { vmin[k] = c; rmin[k] = r; }
            }
        }
        {
            unsigned a0 = (unsigned)rmin[0] | ((unsigned)rmin[1] << 16);
            unsigned a1 = (unsigned)rmin[2] | ((unsigned)rmin[3] << 16);
            unsigned a2 = (unsigned)rmin[4] | ((unsigned)rmin[5] << 16);
            unsigned a3 = (unsigned)rmin[6] | ((unsigned)rmin[7] << 16);
            ((uint4*)srmin)[lane] = make_uint4(a0, a1, a2, a3);
        }
        if (lane < 8) srowt[lane] = 0u;
        __syncwarp();
        // Greedy pre-assignment: column j -> rmin[j] if that row is still free.
        if (lane == 0) {
            for (int j = 0; j < N; ++j) {
                int r = srmin[j];
                unsigned wd = srowt[r >> 5];
                if (!((wd >> (r & 31)) & 1u)) {
                    srowt[r >> 5] = wd | (1u << (r & 31));
                    p_[j + 1] = (unsigned short)(r + 1);
                }
            }
        }
        __syncwarp();

        int vreg[8];
#pragma unroll
        for (int k = 0; k < 8; ++k) vreg[k] = (int)vmin[k];
        unsigned rt[8];
#pragma unroll
        for (int w = 0; w < 8; ++w) rt[w] = srowt[w];

        // base pointer for this lane's 16-byte row slice (offset by t_i*2-512)
        const char* cbase = (const char*)cost - 512 + lane * 16;

        // ---- Dijkstra for each unassigned row ----
        for (int w = 0; w < 8; ++w) {
            unsigned freeb = ~rt[w];
            while (freeb) {
                const int bz = __ffs(freeb) - 1;
                freeb &= freeb - 1;
                const int i = w * 32 + bz + 1;     // 1-based start row; u_[i]==0

                unsigned vpk[8], Dp[8];
                int way[8];
#pragma unroll
                for (int k = 0; k < 8; ++k) {
                    int j = (lane << 3) + k;
                    vpk[k] = (((unsigned)p_[j + 1] << 8) | (unsigned)j)
                             - ((unsigned)vreg[k] << 17);
                    Dp[k] = 0xFFFFFFFFu;
                    way[k] = JROOT;
                }

                unsigned t_i = (unsigned)i << 8;   // = i0 * 256
                int S = 0, u0 = 0, j0 = JROOT, jfinal;

                while (true) {
                    const uint4 cc = *(const uint4*)(cbase + t_i * 2);
                    const unsigned bsh = ((unsigned)(S - u0)) << 17;
                    const unsigned w0 = cc.x, w1 = cc.y, w2 = cc.z, w3 = cc.w;
                    unsigned pre[8];
                    pre[0] = w0 << 17; pre[1] = (w0 << 1) & 0xFFFE0000u;
                    pre[2] = w1 << 17; pre[3] = (w1 << 1) & 0xFFFE0000u;
                    pre[4] = w2 << 17; pre[5] = (w2 << 1) & 0xFFFE0000u;
                    pre[6] = w3 << 17; pre[7] = (w3 << 1) & 0xFFFE0000u;
                    unsigned cand[8];
#pragma unroll
                    for (int k = 0; k < 8; ++k) cand[k] = pre[k] + bsh + vpk[k];
                    bool ge[8];
#pragma unroll
                    for (int k = 0; k < 8; ++k) ge[k] = cand[k] < Dp[k];
#pragma unroll
                    for (int k = 0; k < 8; ++k) Dp[k] = umin(Dp[k], cand[k]);
#pragma unroll
                    for (int k = 0; k < 8; ++k) way[k] = ge[k] ? j0 : way[k];

                    unsigned m01 = Dp[0] < Dp[1] ? Dp[0] : Dp[1];
                    unsigned m23 = Dp[2] < Dp[3] ? Dp[2] : Dp[3];
                    unsigned m45 = Dp[4] < Dp[5] ? Dp[4] : Dp[5];
                    unsigned m67 = Dp[6] < Dp[7] ? Dp[6] : Dp[7];
                    unsigned ma = m01 < m23 ? m01 : m23;
                    unsigned mb = m45 < m67 ? m45 : m67;
                    const unsigned g = __reduce_min_sync(FULL, ma < mb ? ma : mb);

                    t_i = g & 0x1FF00u;                    // p * 256
                    S   = (int)(g >> 17);
                    const int j1 = (int)(g & 0xFFu);
                    if (t_i == 0) { jfinal = j1; break; }
                    u0  = *(const int*)((const char*)u_ + (t_i >> 6));
                    // freeze j1: its future cands land in [2^31,2^32) (no wrap,
                    // QMAX=8191), never win, never beat frozen Dp; Dp bit31
                    // excludes it from the tree.
#pragma unroll
                    for (int k = 0; k < 8; ++k)
                        if (((lane << 3) + k) == j1) {
                            vpk[k] += 0x80000000u;
                            Dp[k]  |= 0x80000000u;
                        }
                    j0 = j1;
                }

                const int mu = S;
                // publish way pointers
                {
                    unsigned a0 = ((unsigned)way[0] & 0xFFFFu) | ((unsigned)way[1] << 16);
                    unsigned a1 = ((unsigned)way[2] & 0xFFFFu) | ((unsigned)way[3] << 16);
                    unsigned a2 = ((unsigned)way[4] & 0xFFFFu) | ((unsigned)way[5] << 16);
                    unsigned a3 = ((unsigned)way[6] & 0xFFFFu) | ((unsigned)way[7] << 16);
                    ((uint4*)way0_)[lane] = make_uint4(a0, a1, a2, a3);
                }
                __syncwarp();
                if (lane == 0) {
                    int cur = jfinal;                      // augment along path
                    while (true) {
                        int pr = way0_[cur];
                        if (pr == JROOT) { p_[cur + 1] = (unsigned short)i; break; }
                        p_[cur + 1] = p_[pr + 1];
                        cur = pr;
                    }
                    u_[i] += mu;
                }
                // deferred dual updates from frozen Dp words.
                // frozen <=> bit31 set and != 0xFFFFFFFF (frozen Dp <= 0xFFFDFFFF).
#pragma unroll
                for (int k = 0; k < 8; ++k) {
                    unsigned dk = Dp[k];
                    if ((dk >> 31) && dk != 0xFFFFFFFFu) {
                        unsigned dv = dk & 0x7FFFFFFFu;
                        int adj = mu - (int)(dv >> 17);
                        vreg[k] -= adj;
                        u_[(dv >> 8) & 0x1FFu] += adj;     // distinct rows: race-free
                    }
                }
                __syncwarp();
            }
        }
    }
    __syncthreads();

    // ---- Phase 3: gather matched fp32 distances, deterministic block sum ----
    {
        const int j   = tid + 1;
        const int row = p_[j];
        float val = g_dist[((size_t)b << 16) + (size_t)(row - 1) * N + (j - 1)];
        double d = (double)val;
#pragma unroll
        for (int off = 16; off > 0; off >>= 1)
            d += __shfl_down_sync(0xffffffffu, d, off);
        if ((tid & 31) == 0) sred[tid >> 5] = d;
        __syncthreads();
        if (tid == 0) {
            double t = 0.0;
#pragma unroll
            for (int w = 0; w < 8; ++w) t += sred[w];   // fixed order
            g_bsum[b] = t;
        }
    }
}

// ---------------------------------------------------------------------------
// Kernel C: deterministic final reduce + mean
// ---------------------------------------------------------------------------
__global__ void finalize_kernel(float* __restrict__ out) {
    double t = 0.0;
#pragma unroll
    for (int b = 0; b < BATCH; ++b) t += g_bsum[b];
    out[0] = (float)(t / (double)(BATCH * N));
}

// ---------------------------------------------------------------------------
extern "C" void kernel_launch(void* const* d_in, const int* in_sizes, int n_in,
                              void* d_out, int out_size) {
    const float* pred = (const float*)d_in[0];
    const float* tgt  = (const float*)d_in[1];
    float* out = (float*)d_out;

    cudaFuncSetAttribute(hungarian_kernel,
                         cudaFuncAttributeMaxDynamicSharedMemorySize, SMEM_B);

    dist_kernel<<<dim3(16, 16, 16), 256>>>(pred, tgt);
    hungarian_kernel<<<BATCH, 256, SMEM_B>>>();
    finalize_kernel<<<1, 1>>>(out);
}

// round 11
// speedup vs baseline: 1.3455x; 1.0012x over previous
#include <cuda_runtime.h>
#include <cuda_bf16.h>

#define BATCH 16
#define N 256
#define DIM 128

// Scratch (device globals: allocation-free per harness rules)
__device__ float          g_dist[BATCH * N * N];   // 4 MB fp32 distances
__device__ unsigned short g_cost[BATCH * N * N];   // 2 MB u16: (quantized c)<<1
__device__ double         g_bsum[BATCH];           // per-batch matched sums

#define QSCALE 128.0f
#define QMAX   4095    // stored value c' = c<<1 <= 8190; d' = S'+rc' < 2^14 (same
                       // packed-domain margins as the passing R10 kernel)

// ---------------------------------------------------------------------------
// Kernel A: pairwise L2 distances + quantization (stored pre-shifted <<1).
// ---------------------------------------------------------------------------
__global__ __launch_bounds__(256) void dist_kernel(const float* __restrict__ pred,
                                                   const float* __restrict__ tgt) {
    __shared__ float sp[16 * 132];
    __shared__ float st[16 * 132];
    const int b  = blockIdx.z;
    const int rt = blockIdx.y;
    const int ct = blockIdx.x;
    const int tid = threadIdx.x;

    const float4* p4 = (const float4*)(pred + (size_t)(b * N + rt * 16) * DIM);
    const float4* t4 = (const float4*)(tgt  + (size_t)(b * N + ct * 16) * DIM);
    for (int idx = tid; idx < 512; idx += 256) {
        int r = idx >> 5, c = idx & 31;
        *(float4*)&sp[r * 132 + c * 4] = p4[idx];
        *(float4*)&st[r * 132 + c * 4] = t4[idx];
    }
    __syncthreads();

    const int ti = tid >> 4;
    const int tj = tid & 15;
    float acc = 0.f;
#pragma unroll
    for (int d4 = 0; d4 < 32; ++d4) {
        float4 a = *(const float4*)&sp[ti * 132 + d4 * 4];
        float4 c = *(const float4*)&st[tj * 132 + d4 * 4];
        float dx = a.x - c.x, dy = a.y - c.y, dz = a.z - c.z, dw = a.w - c.w;
        acc += dx * dx + dy * dy + dz * dz + dw * dw;
    }
    float dd = sqrtf(acc);
    size_t o = ((size_t)b << 16) + (size_t)(rt * 16 + ti) * N + (ct * 16 + tj);
    g_dist[o] = dd;
    int q = __float2int_rn(dd * QSCALE);
    q = q > QMAX ? QMAX : q;
    g_cost[o] = (unsigned short)(q << 1);   // pre-shifted for cheap (c<<17) extract
}

// ---------------------------------------------------------------------------
// Kernel B: per-batch Jonker-Volgenant LSA on pre-shifted u16 costs in shared.
//   Warp-0 Dijkstra, (d<<17 | p<<8 | j) packed redux-min, inline relax.
//   All dual quantities (u, v, S) live pre-shifted by 17:
//     bsh = (g & 0x7FFE0000) - u0sh ;  cand = pre + bsh + vpk (1 IADD3/col)
//     pre[even] = w<<16, pre[odd] = w & 0xFFFF0000  (costs stored <<1)
//   Freeze: vpk += 2^31 (future cands wrap-free >= 2^31, never win, never
//   beat frozen Dp) and Dp |= 2^31 (tree exclusion). Duals decoded from
//   frozen Dp at search end, all in the shifted domain.
// ---------------------------------------------------------------------------
// dynamic smem layout (bytes)
#define OFF_COST 0                       // u16[65536] = 131072
#define OFF_U    131072                  // u32[257]   = 1028  -> 132100
#define OFF_P    132100                  // u16[257]   = 514   -> 132614
#define OFF_WAY  132624                  // u16[256]   = 512   -> 133136 (16-aligned)
#define OFF_RMIN 133136                  // u16[256]   = 512   -> 133648 (16-aligned)
#define OFF_ROWT 133648                  // u32[8]     = 32    -> 133680
#define OFF_SRED 133680                  // double[8]  = 64    -> 133744
#define SMEM_B   133744

#define JROOT 0x1FF                      // way-chain root marker

extern __shared__ char s_raw[];

__global__ __launch_bounds__(256) void hungarian_kernel() {
    const int b   = blockIdx.x;
    const int tid = threadIdx.x;

    unsigned short* cost  = (unsigned short*)(s_raw + OFF_COST);
    unsigned*       u_    = (unsigned*)(s_raw + OFF_U);         // u<<17, 1-based
    unsigned short* p_    = (unsigned short*)(s_raw + OFF_P);   // p_[j+1], 0 = free
    unsigned short* way0_ = (unsigned short*)(s_raw + OFF_WAY); // 0-based cols
    unsigned short* srmin = (unsigned short*)(s_raw + OFF_RMIN);
    unsigned*       srowt = (unsigned*)(s_raw + OFF_ROWT);
    double*         sred  = (double*)(s_raw + OFF_SRED);

    // ---- Phase 1: copy quantized costs into shared, init state ----
    const uint4* csrc = (const uint4*)(g_cost + ((size_t)b << 16));
    uint4* cdst = (uint4*)cost;
    for (int idx = tid; idx < (N * N) / 8; idx += 256) cdst[idx] = csrc[idx];
    for (int i = tid; i < N + 1; i += 256) { u_[i] = 0u; p_[i] = 0; }
    __syncthreads();

    // ---- Phase 2: warp 0 runs the LSA ----
    if (tid < 32) {
        const unsigned FULL = 0xffffffffu;
        const int lane = tid;

        // Column reduction in the stored (c<<1) domain.
        unsigned vmin[8]; int rmin[8];
#pragma unroll
        for (int k = 0; k < 8; ++k) { vmin[k] = 0xFFFFFFFFu; rmin[k] = 0; }
        for (int r = 0; r < N; ++r) {
            uint4 cc = ((const uint4*)(cost + (r << 8)))[lane];
            unsigned wv[4] = {cc.x, cc.y, cc.z, cc.w};
#pragma unroll
            for (int k = 0; k < 8; ++k) {
                unsigned c = (wv[k >> 1] >> ((k & 1) * 16)) & 0xFFFFu;
                if (c < vmin[k]) { vmin[k] = c; rmin[k] = r; }
            }
        }
        {
            unsigned a0 = (unsigned)rmin[0] | ((unsigned)rmin[1] << 16);
            unsigned a1 = (unsigned)rmin[2] | ((unsigned)rmin[3] << 16);
            unsigned a2 = (unsigned)rmin[4] | ((unsigned)rmin[5] << 16);
            unsigned a3 = (unsigned)rmin[6] | ((unsigned)rmin[7] << 16);
            ((uint4*)srmin)[lane] = make_uint4(a0, a1, a2, a3);
        }
        if (lane < 8) srowt[lane] = 0u;
        __syncwarp();
        // Greedy pre-assignment: column j -> rmin[j] if that row is still free.
        if (lane == 0) {
            for (int j = 0; j < N; ++j) {
                int r = srmin[j];
                unsigned wd = srowt[r >> 5];
                if (!((wd >> (r & 31)) & 1u)) {
                    srowt[r >> 5] = wd | (1u << (r & 31));
                    p_[j + 1] = (unsigned short)(r + 1);
                }
            }
        }
        __syncwarp();

        unsigned vsh[8];                   // v<<17 == (stored c')<<16
#pragma unroll
        for (int k = 0; k < 8; ++k) vsh[k] = vmin[k] << 16;
        unsigned rt[8];
#pragma unroll
        for (int w = 0; w < 8; ++w) rt[w] = srowt[w];

        // base pointer for this lane's 16-byte row slice (offset by t_i*2-512)
        const char* cbase = (const char*)cost - 512 + lane * 16;

        // ---- Dijkstra for each unassigned row ----
        for (int w = 0; w < 8; ++w) {
            unsigned freeb = ~rt[w];
            while (freeb) {
                const int bz = __ffs(freeb) - 1;
                freeb &= freeb - 1;
                const int i = w * 32 + bz + 1;     // 1-based start row; u_[i]==0

                unsigned vpk[8], Dp[8];
                int way[8];
#pragma unroll
                for (int k = 0; k < 8; ++k) {
                    int j = (lane << 3) + k;
                    vpk[k] = (((unsigned)p_[j + 1] << 8) | (unsigned)j) - vsh[k];
                    Dp[k] = 0xFFFFFFFFu;
                    way[k] = JROOT;
                }

                unsigned t_i = (unsigned)i << 8;   // = i0 * 256
                unsigned smask = 0u, u0sh = 0u, mush;
                int j0 = JROOT, jfinal;

                while (true) {
                    const uint4 cc = *(const uint4*)(cbase + t_i * 2);
                    const unsigned bsh = smask - u0sh;       // (S-u)<<17 mod 2^32
                    const unsigned w0 = cc.x, w1 = cc.y, w2 = cc.z, w3 = cc.w;
                    unsigned pre[8];
                    pre[0] = w0 << 16; pre[1] = w0 & 0xFFFF0000u;
                    pre[2] = w1 << 16; pre[3] = w1 & 0xFFFF0000u;
                    pre[4] = w2 << 16; pre[5] = w2 & 0xFFFF0000u;
                    pre[6] = w3 << 16; pre[7] = w3 & 0xFFFF0000u;
                    unsigned cand[8];
#pragma unroll
                    for (int k = 0; k < 8; ++k) cand[k] = pre[k] + bsh + vpk[k];
                    bool ge[8];
#pragma unroll
                    for (int k = 0; k < 8; ++k) ge[k] = cand[k] < Dp[k];
#pragma unroll
                    for (int k = 0; k < 8; ++k) Dp[k] = umin(Dp[k], cand[k]);
#pragma unroll
                    for (int k = 0; k < 8; ++k) way[k] = ge[k] ? j0 : way[k];

                    unsigned m01 = Dp[0] < Dp[1] ? Dp[0] : Dp[1];
                    unsigned m23 = Dp[2] < Dp[3] ? Dp[2] : Dp[3];
                    unsigned m45 = Dp[4] < Dp[5] ? Dp[4] : Dp[5];
                    unsigned m67 = Dp[6] < Dp[7] ? Dp[6] : Dp[7];
                    unsigned ma = m01 < m23 ? m01 : m23;
                    unsigned mb = m45 < m67 ? m45 : m67;
                    const unsigned g = __reduce_min_sync(FULL, ma < mb ? ma : mb);

                    t_i   = g & 0x1FF00u;                  // p * 256
                    smask = g & 0x7FFE0000u;               // S<<17
                    const int j1 = (int)(g & 0xFFu);
                    if (t_i == 0) { jfinal = j1; mush = smask; break; }
                    u0sh = *(const unsigned*)((const char*)u_ + (t_i >> 6));
                    // freeze j1: future cands land in [2^31,2^32) wrap-free,
                    // never win, never beat frozen Dp; Dp bit31 excludes it
                    // from the tree.
#pragma unroll
                    for (int k = 0; k < 8; ++k)
                        if (((lane << 3) + k) == j1) {
                            vpk[k] += 0x80000000u;
                            Dp[k]  |= 0x80000000u;
                        }
                    j0 = j1;
                }

                // publish way pointers
                {
                    unsigned a0 = ((unsigned)way[0] & 0xFFFFu) | ((unsigned)way[1] << 16);
                    unsigned a1 = ((unsigned)way[2] & 0xFFFFu) | ((unsigned)way[3] << 16);
                    unsigned a2 = ((unsigned)way[4] & 0xFFFFu) | ((unsigned)way[5] << 16);
                    unsigned a3 = ((unsigned)way[6] & 0xFFFFu) | ((unsigned)way[7] << 16);
                    ((uint4*)way0_)[lane] = make_uint4(a0, a1, a2, a3);
                }
                __syncwarp();
                if (lane == 0) {
                    int cur = jfinal;                      // augment along path
                    while (true) {
                        int pr = way0_[cur];
                        if (pr == JROOT) { p_[cur + 1] = (unsigned short)i; break; }
                        p_[cur + 1] = p_[pr + 1];
                        cur = pr;
                    }
                    u_[i] += mush;
                }
                // deferred dual updates from frozen Dp words (shifted domain).
                // frozen <=> bit31 set and != 0xFFFFFFFF.
#pragma unroll
                for (int k = 0; k < 8; ++k) {
                    unsigned dk = Dp[k];
                    if ((dk >> 31) && dk != 0xFFFFFFFFu) {
                        unsigned adjsh = mush - (dk & 0x7FFE0000u);  // (mu-Sfz)<<17
                        vsh[k] -= adjsh;
                        u_[(dk >> 8) & 0x1FFu] += adjsh;   // distinct rows: race-free
                    }
                }
                __syncwarp();
            }
        }
    }
    __syncthreads();

    // ---- Phase 3: gather matched fp32 distances, deterministic block sum ----
    {
        const int j   = tid + 1;
        const int row = p_[j];
        float val = g_dist[((size_t)b << 16) + (size_t)(row - 1) * N + (j - 1)];
        double d = (double)val;
#pragma unroll
        for (int off = 16; off > 0; off >>= 1)
            d += __shfl_down_sync(0xffffffffu, d, off);
        if ((tid & 31) == 0) sred[tid >> 5] = d;
        __syncthreads();
        if (tid == 0) {
            double t = 0.0;
#pragma unroll
            for (int w = 0; w < 8; ++w) t += sred[w];   // fixed order
            g_bsum[b] = t;
        }
    }
}

// ---------------------------------------------------------------------------
// Kernel C: deterministic final reduce + mean
// ---------------------------------------------------------------------------
__global__ void finalize_kernel(float* __restrict__ out) {
    double t = 0.0;
#pragma unroll
    for (int b = 0; b < BATCH; ++b) t += g_bsum[b];
    out[0] = (float)(t / (double)(BATCH * N));
}

// ---------------------------------------------------------------------------
extern "C" void kernel_launch(void* const* d_in, const int* in_sizes, int n_in,
                              void* d_out, int out_size) {
    const float* pred = (const float*)d_in[0];
    const float* tgt  = (const float*)d_in[1];
    float* out = (float*)d_out;

    cudaFuncSetAttribute(hungarian_kernel,
                         cudaFuncAttributeMaxDynamicSharedMemorySize, SMEM_B);

    dist_kernel<<<dim3(16, 16, 16), 256>>>(pred, tgt);
    hungarian_kernel<<<BATCH, 256, SMEM_B>>>();
    finalize_kernel<<<1, 1>>>(out);
}